// round 7
// baseline (speedup 1.0000x reference)
#include <cuda_runtime.h>

#define BATCH 4
#define NINST 32
#define HW (512*512)

typedef unsigned long long ull;

// t-binning: tp2 = t+2 in [2,66]; bin = (bits(tp2)>>10) - TOFF; 2048-slot guard below
#define TB_HI 1089792u             // bits(66.0f)>>10 = 0x42840000>>10
#define TOFF  1046528u             // (0x40000000>>10) - 2048 guard
#define NBT   45056                // 44*1024 >= TB_HI-TOFF+1 = 43265

// e-histogram: float-bit bins of e in [0,2], >>12 (rel width 4.9e-4), packed pos<<32|neg
#define EB_SHIFT 12
#define EB_HALF 2048u
#define EB_TOP 262144              // bits(2.0f)>>12
#define NBE 263168                 // 257*1024
#define EPT 257                    // e-bins per thread in epilogue

static __device__ unsigned int g_thist[BATCH][NBT];
static __device__ ull          g_hist[BATCH][NBE];
static __device__ double       g_sum[BATCH][NINST][4];   // sx, sy, ssig, ssig2
static __device__ unsigned int g_cnt[BATCH][NINST];
static __device__ ull          g_prm2[BATCH][NINST][4];  // A, Bx, By, C+2 duplicated f32x2
static __device__ double       g_var[BATCH];
static __device__ double       g_res[BATCH];
static __device__ unsigned int g_P[BATCH];
static __device__ int          g_lab64;
static __device__ unsigned int g_ctr_stats;
static __device__ unsigned int g_ctr_epi;

__constant__ ull c_prm2[BATCH][NINST][4];

// ---------------------------------------------------------------- helpers
__device__ __forceinline__ ull fma2(ull a, ull b, ull c) {
    ull d; asm("fma.rn.f32x2 %0, %1, %2, %3;" : "=l"(d) : "l"(a), "l"(b), "l"(c)); return d;
}
__device__ __forceinline__ ull mul2(ull a, ull b) {
    ull d; asm("mul.rn.f32x2 %0, %1, %2;" : "=l"(d) : "l"(a), "l"(b)); return d;
}
__device__ __forceinline__ ull dupf(float f) {
    unsigned u = __float_as_uint(f); return ((ull)u << 32) | u;
}
__device__ __forceinline__ float lane(ull v, int hi) {
    return __uint_as_float(hi ? (unsigned)(v >> 32) : (unsigned)v);
}
__device__ __forceinline__ unsigned tslot(unsigned bits) {   // clamped bit-bin (pre-TOFF)
    return min(bits >> 10, TB_HI);
}
__device__ __forceinline__ unsigned ebin(float e) {
    int s = ((int)__float_as_uint(e)) >> EB_SHIFT;
    return (unsigned)min(max(s, 0), (int)EB_TOP);
}
__device__ __forceinline__ int load_lab(const int* __restrict__ lab32, int idx, int f64) {
    return lab32[f64 ? (idx << 1) : idx];
}

// ---------------------------------------------------------------- init: zero all scratch + label dtype sniff
__global__ void k_init(const int* __restrict__ lab32) {
    size_t stride = (size_t)gridDim.x * blockDim.x;
    size_t i = (size_t)blockIdx.x * blockDim.x + threadIdx.x;
    ull* th = (ull*)&g_thist[0][0];
    const size_t nt = (size_t)BATCH * NBT / 2;
    for (size_t k = i; k < nt; k += stride) th[k] = 0ULL;
    ull* eh = &g_hist[0][0];
    const size_t ne = (size_t)BATCH * NBE;
    for (size_t k = i; k < ne; k += stride) eh[k] = 0ULL;
    if (i < BATCH * NINST * 4) (&g_sum[0][0][0])[i] = 0.0;
    if (i < BATCH * NINST)     (&g_cnt[0][0])[i] = 0u;
    if (i < BATCH)             { g_var[i] = 0.0; g_res[i] = 0.0; }
    if (i == 0)                { g_ctr_stats = 0u; g_ctr_epi = 0u; }
    // label dtype sniff in block 0 (first 256 odd words all zero <=> int64)
    if (blockIdx.x == 0 && threadIdx.x < 256) {
        __shared__ int s_or;
        if (threadIdx.x == 0) s_or = 0;
        __syncthreads();
        int v = lab32[2 * threadIdx.x + 1];
        #pragma unroll
        for (int o = 16; o; o >>= 1) v |= __shfl_down_sync(0xffffffffu, v, o);
        if ((threadIdx.x & 31) == 0) atomicOr(&s_or, v);
        __syncthreads();
        if (threadIdx.x == 0) g_lab64 = (s_or == 0) ? 1 : 0;
    }
}

// ---------------------------------------------------------------- stats + last-block finalize
__global__ void k_stats(const float* __restrict__ emb,
                        const float* __restrict__ sig,
                        const int* __restrict__ lab32) {
    int b = blockIdx.y;
    int base = blockIdx.x * 1024;
    __shared__ float s_sx[NINST], s_sy[NINST], s_ss[NINST], s_ss2[NINST];
    __shared__ unsigned int s_c[NINST];
    __shared__ bool isLast;
    if (threadIdx.x < NINST) {
        s_sx[threadIdx.x] = 0.f; s_sy[threadIdx.x] = 0.f;
        s_ss[threadIdx.x] = 0.f; s_ss2[threadIdx.x] = 0.f;
        s_c[threadIdx.x] = 0u;
    }
    __syncthreads();
    int f64 = g_lab64;
    #pragma unroll
    for (int k = 0; k < 4; k++) {
        int pix = base + threadIdx.x + k * 256;
        int g = load_lab(lab32, b * HW + pix, f64);
        if (g > 0 && g <= NINST) {
            int n = g - 1;
            float ex = emb[(b * 2 + 0) * HW + pix];
            float ey = emb[(b * 2 + 1) * HW + pix];
            float s  = sig[b * HW + pix];
            atomicAdd(&s_sx[n], ex);
            atomicAdd(&s_sy[n], ey);
            atomicAdd(&s_ss[n], s);
            atomicAdd(&s_ss2[n], s * s);
            atomicAdd(&s_c[n], 1u);
        }
    }
    __syncthreads();
    if (threadIdx.x < NINST) {
        int n = threadIdx.x;
        if (s_c[n]) {
            atomicAdd(&g_sum[b][n][0], (double)s_sx[n]);
            atomicAdd(&g_sum[b][n][1], (double)s_sy[n]);
            atomicAdd(&g_sum[b][n][2], (double)s_ss[n]);
            atomicAdd(&g_sum[b][n][3], (double)s_ss2[n]);
            atomicAdd(&g_cnt[b][n], s_c[n]);
        }
    }
    // make this block's atomics globally visible before counter inc
    __threadfence();
    __syncthreads();
    if (threadIdx.x == 0)
        isLast = (atomicInc(&g_ctr_stats, 0xFFFFFFFFu) == 256u * BATCH - 1u);
    __syncthreads();
    if (isLast && threadIdx.x < 128) {
        int t = threadIdx.x;         // bb = warp, n = lane
        int bb = t >> 5, n = t & 31;
        double c  = (double)g_cnt[bb][n];
        double ic = (c > 0.0) ? (1.0 / c) : 0.0;
        double cx = g_sum[bb][n][0] * ic;
        double cy = g_sum[bb][n][1] * ic;
        double m  = g_sum[bb][n][2] * ic;
        double vp = g_sum[bb][n][3] - c * m * m;
        float Af = 0.f, Bxf = 0.f, Byf = 0.f, Cf = 2.f;
        if (m > 0.0) {
            double A = 0.5 / (m * m);       // t = A*d^2; store C+2 (offset binning)
            Af  = (float)A;
            Bxf = (float)(-2.0 * cx * A);
            Byf = (float)(-2.0 * cy * A);
            Cf  = (float)((cx * cx + cy * cy) * A + 2.0);
        }
        g_prm2[bb][n][0] = dupf(Af);
        g_prm2[bb][n][1] = dupf(Bxf);
        g_prm2[bb][n][2] = dupf(Byf);
        g_prm2[bb][n][3] = dupf(Cf);
        unsigned cc = g_cnt[bb][n];
        double icsum = ic;
        #pragma unroll
        for (int o = 16; o; o >>= 1) {
            vp    += __shfl_down_sync(0xffffffffu, vp, o);
            icsum += __shfl_down_sync(0xffffffffu, icsum, o);
            cc    += __shfl_down_sync(0xffffffffu, cc, o);
        }
        if (n == 0) {
            g_var[bb] = vp * icsum / (double)NINST;
            g_P[bb]   = cc;
        }
    }
}

// ---------------------------------------------------------------- main: 4 px/thread, params via constant (LDCU)
__global__ void k_main(const float* __restrict__ emb,
                       const int* __restrict__ lab32) {
    int b = blockIdx.y;
    __shared__ ull sp2[NINST][4];   // for divergent positive path only
    if (threadIdx.x < NINST * 2) {
        ((ull*)sp2)[threadIdx.x * 2 + 0] = ((ull*)g_prm2[b])[threadIdx.x * 2 + 0];
        ((ull*)sp2)[threadIdx.x * 2 + 1] = ((ull*)g_prm2[b])[threadIdx.x * 2 + 1];
    }
    __syncthreads();
    int pix0 = (blockIdx.x * blockDim.x + threadIdx.x) * 4;
    const ulonglong2 exv = *(const ulonglong2*)(emb + (size_t)(b * 2 + 0) * HW + pix0);
    const ulonglong2 eyv = *(const ulonglong2*)(emb + (size_t)(b * 2 + 1) * HW + pix0);
    ull exa = exv.x, exb = exv.y, eya = eyv.x, eyb = eyv.y;
    ull qa = fma2(exa, exa, mul2(eya, eya));
    ull qb = fma2(exb, exb, mul2(eyb, eyb));
    unsigned int* hba = &g_thist[b][0] - TOFF;   // fold -TOFF into base
    #pragma unroll 8
    for (int n = 0; n < NINST; n++) {
        ull A2 = c_prm2[b][n][0], Bx2 = c_prm2[b][n][1];
        ull By2 = c_prm2[b][n][2], C2 = c_prm2[b][n][3];
        ull ta = fma2(Bx2, exa, fma2(By2, eya, fma2(A2, qa, C2)));
        ull tb = fma2(Bx2, exb, fma2(By2, eyb, fma2(A2, qb, C2)));
        atomicAdd(&hba[tslot((unsigned)ta)], 1u);
        atomicAdd(&hba[tslot((unsigned)(ta >> 32))], 1u);
        atomicAdd(&hba[tslot((unsigned)tb)], 1u);
        atomicAdd(&hba[tslot((unsigned)(tb >> 32))], 1u);
    }
    // positive fixups (one pair per labeled pixel)
    int f64 = g_lab64;
    #pragma unroll
    for (int k = 0; k < 4; k++) {
        int g = load_lab(lab32, b * HW + pix0 + k, f64);
        if (g > 0 && g <= NINST) {
            int n = g - 1;
            float A  = lane(sp2[n][0], 0), Bx = lane(sp2[n][1], 0);
            float By = lane(sp2[n][2], 0), C  = lane(sp2[n][3], 0);
            float ex = lane(k < 2 ? exa : exb, k & 1);
            float ey = lane(k < 2 ? eya : eyb, k & 1);
            float q  = fmaf(ex, ex, ey * ey);            // bit-identical to f32x2 lane
            float tp2 = fmaf(Bx, ex, fmaf(By, ey, fmaf(A, q, C)));
            atomicAdd(&hba[tslot(__float_as_uint(tp2))], 0xFFFFFFFFu);  // cancel false negative
            float e = fmaf(-2.f, __expf(2.0f - tp2), 2.0f);             // 2 - 2*exp(-t)
            atomicAdd(&g_hist[b][ebin(e)], 1ULL << 32);
        }
    }
}

// ---------------------------------------------------------------- epilogue: conv + scan + Lovasz + output
__global__ void __launch_bounds__(1024, 1) k_epi(float* __restrict__ out) {
    int b = blockIdx.x;
    int t = threadIdx.x;
    __shared__ ull ss[1024];

    // Phase 1: t-hist -> e-hist (negatives)
    #pragma unroll 4
    for (int k = 0; k < NBT / 1024; k++) {
        int i = k * 1024 + t;
        unsigned c = g_thist[b][i];
        if (c) {
            float tp2 = __uint_as_float((((unsigned)i + TOFF) << 10) + 512u);  // bin-center t+2
            float e = 2.f * __expf(2.0f - tp2);                                // 2*exp(-t)
            atomicAdd(&g_hist[b][ebin(e)], (ull)c);
        }
    }
    __threadfence();
    __syncthreads();

    // Phase 2a: per-thread segment sums (descending e; thread t covers positions t*EPT..)
    const ull* hb = g_hist[b];
    ull segsum = 0;
    {
        int bin0 = NBE - 1 - t * EPT;
        for (int k = 0; k < EPT; k++) segsum += hb[bin0 - k];
    }
    // Phase 2b: block-wide inclusive scan over 1024 segment sums
    ss[t] = segsum; __syncthreads();
    for (int o = 1; o < 1024; o <<= 1) {
        ull u = (t >= o) ? ss[t - o] : 0ULL;
        __syncthreads();
        ss[t] += u;
        __syncthreads();
    }
    ull pref = ss[t] - segsum;                    // strictly-above counts
    unsigned pp = (unsigned)(pref >> 32);
    unsigned nn = (unsigned)(pref & 0xffffffffu);
    unsigned P  = g_P[b];
    // Phase 2c: walk own segment descending, accumulate e * deltaJaccard
    float contrib = 0.f;
    {
        int bin0 = NBE - 1 - t * EPT;
        for (int k = 0; k < EPT; k++) {
            ull v = hb[bin0 - k];
            if (v) {
                unsigned a  = (unsigned)(v >> 32);
                unsigned gn = (unsigned)v;
                float e = __uint_as_float(((unsigned)(bin0 - k) << EB_SHIFT) + EB_HALF);
                e = fminf(e, 2.0f);
                float A   = (float)(P - pp);
                float U1  = (float)(P + nn);
                float U2  = U1 + (float)gn;
                float num = A * (float)gn + (float)a * U1;
                contrib += e * num / (U1 * U2);
                pp += a; nn += gn;
            }
        }
    }
    // Phase 2d: block reduce
    float* sc = (float*)ss;
    __syncthreads();
    sc[t] = contrib; __syncthreads();
    for (int o = 512; o; o >>= 1) {
        if (t < o) sc[t] += sc[t + o];
        __syncthreads();
    }
    if (t == 0) {
        g_res[b] = (double)sc[0] + g_var[b];
        __threadfence();
        if (atomicInc(&g_ctr_epi, 0xFFFFFFFFu) == BATCH - 1) {
            double acc = 0.0;
            #pragma unroll
            for (int bb = 0; bb < BATCH; bb++) acc += g_res[bb];
            out[0] = (float)(acc / (double)BATCH);
        }
    }
}

extern "C" void kernel_launch(void* const* d_in, const int* in_sizes, int n_in,
                              void* d_out, int out_size) {
    const float* emb = (const float*)d_in[0];
    const float* sig = (const float*)d_in[1];
    const int* lab32 = (const int*)d_in[2];
    float* out = (float*)d_out;
    (void)in_sizes; (void)n_in; (void)out_size;

    k_init<<<64, 1024>>>(lab32);
    k_stats<<<dim3(256, BATCH), 256>>>(emb, sig, lab32);
    void* src = nullptr;
    cudaGetSymbolAddress(&src, g_prm2);
    cudaMemcpyToSymbolAsync(c_prm2, src, sizeof(c_prm2), 0, cudaMemcpyDeviceToDevice);
    k_main<<<dim3(HW / 1024, BATCH), 256>>>(emb, lab32);
    k_epi<<<BATCH, 1024>>>(out);
}

// round 8
// speedup vs baseline: 1.4982x; 1.4982x over previous
#include <cuda_runtime.h>

#define BATCH 4
#define NINST 32
#define HW (512*512)

typedef unsigned long long ull;

// t-binning: tp2 = t+2 in [2,66]; slot = (bits(tp2)>>10), stored at base-TOFF
#define TB_HI 1089792u             // bits(66.0f)>>10
#define TOFF  1046528u             // (0x40000000>>10) - 2048 guard
#define NBT   45056                // 44*1024 >= TB_HI-TOFF+1

// e-histogram: float-bit bins of e in [0,2], >>12, packed pos<<32|neg
#define EB_SHIFT 12
#define EB_HALF 2048u
#define EB_TOP 262144              // bits(2.0f)>>12
#define CHUNK 4096
#define NCHUNK 65
#define NBE (NCHUNK*CHUNK)         // 266240 > EB_TOP

static __device__ unsigned int g_thist[BATCH][NBT];
static __device__ ull          g_hist[BATCH][NBE];
static __device__ double       g_sum[BATCH][NINST][4];
static __device__ unsigned int g_cnt[BATCH][NINST];
static __device__ ull          g_prm2[BATCH][NINST][4];  // A, Bx, By, C+2 dup f32x2
static __device__ double       g_var[BATCH];
static __device__ double       g_res[BATCH];
static __device__ unsigned int g_P[BATCH];
static __device__ ull          g_chunksum[BATCH][NCHUNK];
static __device__ ull          g_chunkpre[BATCH][NCHUNK];
static __device__ int          g_lab64;
static __device__ unsigned int g_ctr_stats;
static __device__ unsigned int g_ctr_loss;

__constant__ ull c_prm2[BATCH][NINST][4];

// ---------------------------------------------------------------- helpers
__device__ __forceinline__ ull fma2(ull a, ull b, ull c) {
    ull d; asm("fma.rn.f32x2 %0, %1, %2, %3;" : "=l"(d) : "l"(a), "l"(b), "l"(c)); return d;
}
__device__ __forceinline__ ull mul2(ull a, ull b) {
    ull d; asm("mul.rn.f32x2 %0, %1, %2;" : "=l"(d) : "l"(a), "l"(b)); return d;
}
__device__ __forceinline__ ull dupf(float f) {
    unsigned u = __float_as_uint(f); return ((ull)u << 32) | u;
}
__device__ __forceinline__ float lane(ull v, int hi) {
    return __uint_as_float(hi ? (unsigned)(v >> 32) : (unsigned)v);
}
__device__ __forceinline__ unsigned tslot(unsigned bits) {
    return min(bits >> 10, TB_HI);
}
__device__ __forceinline__ unsigned ebin(float e) {
    int s = ((int)__float_as_uint(e)) >> EB_SHIFT;
    return (unsigned)min(max(s, 0), (int)EB_TOP);
}
__device__ __forceinline__ int load_lab(const int* __restrict__ lab32, int idx, int f64) {
    return lab32[f64 ? (idx << 1) : idx];
}

// ---------------------------------------------------------------- init: zero scratch + label dtype sniff
__global__ void k_init(const int* __restrict__ lab32) {
    size_t stride = (size_t)gridDim.x * blockDim.x;
    size_t i = (size_t)blockIdx.x * blockDim.x + threadIdx.x;
    ull* th = (ull*)&g_thist[0][0];
    const size_t nt = (size_t)BATCH * NBT / 2;
    for (size_t k = i; k < nt; k += stride) th[k] = 0ULL;
    ull* eh = &g_hist[0][0];
    const size_t ne = (size_t)BATCH * NBE;
    for (size_t k = i; k < ne; k += stride) eh[k] = 0ULL;
    if (i < BATCH * NINST * 4) (&g_sum[0][0][0])[i] = 0.0;
    if (i < BATCH * NINST)     (&g_cnt[0][0])[i] = 0u;
    if (i < BATCH)             { g_var[i] = 0.0; g_res[i] = 0.0; }
    if (i == 0)                { g_ctr_stats = 0u; g_ctr_loss = 0u; }
    if (blockIdx.x == 0 && threadIdx.x < 256) {
        __shared__ int s_or;
        if (threadIdx.x == 0) s_or = 0;
        __syncthreads();
        int v = lab32[2 * threadIdx.x + 1];
        #pragma unroll
        for (int o = 16; o; o >>= 1) v |= __shfl_down_sync(0xffffffffu, v, o);
        if ((threadIdx.x & 31) == 0) atomicOr(&s_or, v);
        __syncthreads();
        if (threadIdx.x == 0) g_lab64 = (s_or == 0) ? 1 : 0;
    }
}

// ---------------------------------------------------------------- stats + last-block finalize
__global__ void k_stats(const float* __restrict__ emb,
                        const float* __restrict__ sig,
                        const int* __restrict__ lab32) {
    int b = blockIdx.y;
    int base = blockIdx.x * 1024;
    __shared__ float s_sx[NINST], s_sy[NINST], s_ss[NINST], s_ss2[NINST];
    __shared__ unsigned int s_c[NINST];
    __shared__ bool isLast;
    if (threadIdx.x < NINST) {
        s_sx[threadIdx.x] = 0.f; s_sy[threadIdx.x] = 0.f;
        s_ss[threadIdx.x] = 0.f; s_ss2[threadIdx.x] = 0.f;
        s_c[threadIdx.x] = 0u;
    }
    __syncthreads();
    int f64 = g_lab64;
    #pragma unroll
    for (int k = 0; k < 4; k++) {
        int pix = base + threadIdx.x + k * 256;
        int g = load_lab(lab32, b * HW + pix, f64);
        if (g > 0 && g <= NINST) {
            int n = g - 1;
            float ex = emb[(b * 2 + 0) * HW + pix];
            float ey = emb[(b * 2 + 1) * HW + pix];
            float s  = sig[b * HW + pix];
            atomicAdd(&s_sx[n], ex);
            atomicAdd(&s_sy[n], ey);
            atomicAdd(&s_ss[n], s);
            atomicAdd(&s_ss2[n], s * s);
            atomicAdd(&s_c[n], 1u);
        }
    }
    __syncthreads();
    if (threadIdx.x < NINST) {
        int n = threadIdx.x;
        if (s_c[n]) {
            atomicAdd(&g_sum[b][n][0], (double)s_sx[n]);
            atomicAdd(&g_sum[b][n][1], (double)s_sy[n]);
            atomicAdd(&g_sum[b][n][2], (double)s_ss[n]);
            atomicAdd(&g_sum[b][n][3], (double)s_ss2[n]);
            atomicAdd(&g_cnt[b][n], s_c[n]);
        }
    }
    __threadfence();
    __syncthreads();
    if (threadIdx.x == 0)
        isLast = (atomicInc(&g_ctr_stats, 0xFFFFFFFFu) == 256u * BATCH - 1u);
    __syncthreads();
    if (isLast && threadIdx.x < 128) {
        int t = threadIdx.x;
        int bb = t >> 5, n = t & 31;
        double c  = (double)g_cnt[bb][n];
        double ic = (c > 0.0) ? (1.0 / c) : 0.0;
        double cx = g_sum[bb][n][0] * ic;
        double cy = g_sum[bb][n][1] * ic;
        double m  = g_sum[bb][n][2] * ic;
        double vp = g_sum[bb][n][3] - c * m * m;
        float Af = 0.f, Bxf = 0.f, Byf = 0.f, Cf = 2.f;
        if (m > 0.0) {
            double A = 0.5 / (m * m);       // t = A*d^2; store C+2 (offset binning)
            Af  = (float)A;
            Bxf = (float)(-2.0 * cx * A);
            Byf = (float)(-2.0 * cy * A);
            Cf  = (float)((cx * cx + cy * cy) * A + 2.0);
        }
        g_prm2[bb][n][0] = dupf(Af);
        g_prm2[bb][n][1] = dupf(Bxf);
        g_prm2[bb][n][2] = dupf(Byf);
        g_prm2[bb][n][3] = dupf(Cf);
        unsigned cc = g_cnt[bb][n];
        double icsum = ic;
        #pragma unroll
        for (int o = 16; o; o >>= 1) {
            vp    += __shfl_down_sync(0xffffffffu, vp, o);
            icsum += __shfl_down_sync(0xffffffffu, icsum, o);
            cc    += __shfl_down_sync(0xffffffffu, cc, o);
        }
        if (n == 0) {
            g_var[bb] = vp * icsum / (double)NINST;
            g_P[bb]   = cc;
        }
    }
}

// ---------------------------------------------------------------- main: 8 px/thread
__global__ void k_main(const float* __restrict__ emb,
                       const int* __restrict__ lab32) {
    int b = blockIdx.y;
    __shared__ ull sp2[NINST][4];   // for divergent positive path only
    if (threadIdx.x < NINST * 2) {
        ((ull*)sp2)[threadIdx.x * 2 + 0] = ((ull*)g_prm2[b])[threadIdx.x * 2 + 0];
        ((ull*)sp2)[threadIdx.x * 2 + 1] = ((ull*)g_prm2[b])[threadIdx.x * 2 + 1];
    }
    __syncthreads();
    int pix0 = (blockIdx.x * blockDim.x + threadIdx.x) * 8;
    const float* ebase = emb + (size_t)(b * 2) * HW + pix0;
    ulonglong2 x0 = *(const ulonglong2*)(ebase);
    ulonglong2 x1 = *(const ulonglong2*)(ebase + 4);
    ulonglong2 y0 = *(const ulonglong2*)(ebase + HW);
    ulonglong2 y1 = *(const ulonglong2*)(ebase + HW + 4);
    ull ex[4] = { x0.x, x0.y, x1.x, x1.y };
    ull ey[4] = { y0.x, y0.y, y1.x, y1.y };
    ull q[4];
    #pragma unroll
    for (int j = 0; j < 4; j++) q[j] = fma2(ex[j], ex[j], mul2(ey[j], ey[j]));
    unsigned int* hba = &g_thist[b][0] - TOFF;
    #pragma unroll 4
    for (int n = 0; n < NINST; n++) {
        ull A2 = c_prm2[b][n][0], Bx2 = c_prm2[b][n][1];
        ull By2 = c_prm2[b][n][2], C2 = c_prm2[b][n][3];
        #pragma unroll
        for (int j = 0; j < 4; j++) {
            ull t2 = fma2(Bx2, ex[j], fma2(By2, ey[j], fma2(A2, q[j], C2)));
            atomicAdd(&hba[tslot((unsigned)t2)], 1u);
            atomicAdd(&hba[tslot((unsigned)(t2 >> 32))], 1u);
        }
    }
    // positive fixups
    int f64 = g_lab64;
    #pragma unroll
    for (int k = 0; k < 8; k++) {
        int g = load_lab(lab32, b * HW + pix0 + k, f64);
        if (g > 0 && g <= NINST) {
            int n = g - 1;
            float A  = lane(sp2[n][0], 0), Bx = lane(sp2[n][1], 0);
            float By = lane(sp2[n][2], 0), C  = lane(sp2[n][3], 0);
            float exs = lane(ex[k >> 1], k & 1);
            float eys = lane(ey[k >> 1], k & 1);
            float qs  = fmaf(exs, exs, eys * eys);       // bit-identical to f32x2 lane
            float tp2 = fmaf(Bx, exs, fmaf(By, eys, fmaf(A, qs, C)));
            atomicAdd(&hba[tslot(__float_as_uint(tp2))], 0xFFFFFFFFu);
            float e = fmaf(-2.f, __expf(2.0f - tp2), 2.0f);
            atomicAdd(&g_hist[b][ebin(e)], 1ULL << 32);
        }
    }
}

// ---------------------------------------------------------------- convert t-hist -> e-hist (neg field)
__global__ void k_conv() {
    int b = blockIdx.y;
    int i0 = (blockIdx.x * blockDim.x + threadIdx.x) * 4;
    uint4 c4 = *(const uint4*)&g_thist[b][i0];
    #pragma unroll
    for (int k = 0; k < 4; k++) {
        unsigned c = (&c4.x)[k];
        if (c) {
            float tp2 = __uint_as_float((((unsigned)(i0 + k) + TOFF) << 10) + 512u);
            float e = 2.f * __expf(2.0f - tp2);
            atomicAdd(&g_hist[b][ebin(e)], (ull)c);
        }
    }
}

// ---------------------------------------------------------------- chunk sums over e-hist (wide grid)
__global__ void k_chunksum() {
    int b = blockIdx.y, c = blockIdx.x;
    const ull* hb = g_hist[b] + (size_t)c * CHUNK;
    ull acc = 0;
    for (int i = threadIdx.x; i < CHUNK; i += blockDim.x) acc += hb[i];
    __shared__ ull ss[256];
    ss[threadIdx.x] = acc; __syncthreads();
    for (int o = 128; o; o >>= 1) {
        if (threadIdx.x < o) ss[threadIdx.x] += ss[threadIdx.x + o];
        __syncthreads();
    }
    if (threadIdx.x == 0) g_chunksum[b][c] = ss[0];
}

// ---------------------------------------------------------------- exclusive scan over chunks (descending e)
__global__ void k_scan() {
    int b = blockIdx.x;
    int t = threadIdx.x;               // 128 threads, NCHUNK=65 reversed
    __shared__ ull ss[128];
    ull v = (t < NCHUNK) ? g_chunksum[b][NCHUNK - 1 - t] : 0ULL;
    ss[t] = v; __syncthreads();
    for (int o = 1; o < 128; o <<= 1) {
        ull u = (t >= o) ? ss[t - o] : 0ULL;
        __syncthreads();
        ss[t] += u;
        __syncthreads();
    }
    if (t < NCHUNK) g_chunkpre[b][NCHUNK - 1 - t] = ss[t] - v;
}

// ---------------------------------------------------------------- per-bin Lovasz + final output
__global__ void k_loss(float* __restrict__ out) {
    const int SEG = CHUNK / 256;   // 16 bins per thread, descending order
    int b = blockIdx.y, c = blockIdx.x;
    int t = threadIdx.x;
    int top = c * CHUNK + CHUNK - t * SEG;
    const ull* hb = g_hist[b];
    ull vals[SEG];
    ull segsum = 0;
    #pragma unroll
    for (int k = 0; k < SEG; k++) { vals[k] = hb[top - 1 - k]; segsum += vals[k]; }

    __shared__ ull ss[256];
    ss[t] = segsum; __syncthreads();
    #pragma unroll
    for (int o = 1; o < 256; o <<= 1) {
        ull u = (t >= o) ? ss[t - o] : 0ULL;
        __syncthreads();
        ss[t] += u;
        __syncthreads();
    }
    ull pref = g_chunkpre[b][c] + (ss[t] - segsum);
    unsigned pp = (unsigned)(pref >> 32);
    unsigned nn = (unsigned)(pref & 0xffffffffu);
    unsigned P  = g_P[b];
    float contrib = 0.f;
    #pragma unroll
    for (int k = 0; k < SEG; k++) {
        ull v = vals[k];
        if (v) {
            unsigned a  = (unsigned)(v >> 32);
            unsigned gn = (unsigned)v;
            unsigned bin = (unsigned)(top - 1 - k);
            float e = __uint_as_float((bin << EB_SHIFT) + EB_HALF);
            e = fminf(e, 2.0f);
            float A   = (float)(P - pp);
            float U1  = (float)(P + nn);
            float U2  = U1 + (float)gn;
            float num = A * (float)gn + (float)a * U1;
            contrib += e * num / (U1 * U2);
            pp += a; nn += gn;
        }
    }
    __shared__ float sc[256];
    sc[t] = contrib; __syncthreads();
    for (int o = 128; o; o >>= 1) {
        if (t < o) sc[t] += sc[t + o];
        __syncthreads();
    }
    __shared__ bool isLast;
    if (t == 0) {
        atomicAdd(&g_res[b], (double)sc[0]);
        __threadfence();
        isLast = (atomicInc(&g_ctr_loss, 0xFFFFFFFFu) == (unsigned)(NCHUNK * BATCH) - 1u);
    }
    __syncthreads();
    if (isLast && t == 0) {
        double acc = 0.0;
        #pragma unroll
        for (int bb = 0; bb < BATCH; bb++) acc += g_res[bb] + g_var[bb];
        out[0] = (float)(acc / (double)BATCH);
    }
}

extern "C" void kernel_launch(void* const* d_in, const int* in_sizes, int n_in,
                              void* d_out, int out_size) {
    const float* emb = (const float*)d_in[0];
    const float* sig = (const float*)d_in[1];
    const int* lab32 = (const int*)d_in[2];
    float* out = (float*)d_out;
    (void)in_sizes; (void)n_in; (void)out_size;

    k_init<<<64, 1024>>>(lab32);
    k_stats<<<dim3(256, BATCH), 256>>>(emb, sig, lab32);
    void* src = nullptr;
    cudaGetSymbolAddress(&src, g_prm2);
    cudaMemcpyToSymbolAsync(c_prm2, src, sizeof(c_prm2), 0, cudaMemcpyDeviceToDevice);
    k_main<<<dim3(HW / 2048, BATCH), 256>>>(emb, lab32);
    k_conv<<<dim3(NBT / 1024, BATCH), 256>>>();
    k_chunksum<<<dim3(NCHUNK, BATCH), 256>>>();
    k_scan<<<BATCH, 128>>>();
    k_loss<<<dim3(NCHUNK, BATCH), 256>>>(out);
}